// round 13
// baseline (speedup 1.0000x reference)
#include <cuda_runtime.h>
#include <cuda_fp16.h>
#include <math.h>
#include <stdint.h>

// BiRNN (2-layer bidirectional LSTM), B=32, T=512, H=1024.
// Round 13: (a) GEMM 3-stage cp.async pipeline (KT=32), (b) per-direction
// grid barrier in the recurrent kernel. Math identical to round 12.

#define Bsz 32
#define Tsz 512
#define Hsz 1024
#define G4  4096
#define MROWS (Tsz * Bsz) // 16384

// big input GEMM tiling (round-10 load map, 3 stages)
#define MT 128
#define NT 128
#define KT 32
#define KP 40                     // smem pitch in fp16 (80B)
#define BUFB (MT * KP * 2)        // 10240
#define STAGEB (3 * BUFB)         // A, Bh, Bl = 30720
#define SMEM_GEMM (3 * STAGEB)    // 92160 (2 blocks/SM still fit)

// recurrent tiling: K-tile 128 fp16 (256B) padded to 272B pitch
#define RPB 272
#define R_SA (32 * RPB)                 // 8704  (one A tile)
#define R_TILEB (64 * RPB)              // 17408 (one B tile)
#define R_RES (8 * R_TILEB)             // resident Whh: 139264
#define OFF_A R_RES                     // full A: 8 tiles
#define OFF_GATES (OFF_A + 8 * R_SA)    // 208896
#define GATE_P 68
#define OFF_C (OFF_GATES + 32 * GATE_P * 4) // 217600
#define SMEM_R (OFF_C + 2048)               // 219648

// ---------------- device globals -------------------------------------------
__device__ float g_G[2][(size_t)MROWS * G4];                 // x-part gates + bias
__device__ __align__(256) __half g_A16[2][(size_t)MROWS * Hsz];   // activations fp16
__device__ __align__(256) __half g_Wh16[2][(size_t)G4 * Hsz];     // Wih hi
__device__ __align__(256) __half g_Wl16[2][(size_t)G4 * Hsz];     // Wih lo
__device__ __align__(256) __half g_Rh16[2][(size_t)G4 * Hsz];     // Whh fp16 (reordered)
__device__ __align__(256) __half g_h16[2][2][Bsz * Hsz];          // [parity][dir]
// per-direction barrier state (padded to separate cache lines)
__device__ unsigned g_dcnt[2][4][64];      // leaf counters, 256B apart
__device__ unsigned g_dcnt2[2][64];        // second level
__device__ volatile unsigned g_dgen[2][64];// generation word

// ---------------- helpers ---------------------------------------------------
__device__ __forceinline__ uint32_t smem_u32(const void* p) {
    uint32_t a;
    asm("{ .reg .u64 t; cvta.to.shared.u64 t, %1; cvt.u32.u64 %0, t; }" : "=r"(a) : "l"(p));
    return a;
}
__device__ __forceinline__ void cp16(uint32_t dst, const void* src) {
    asm volatile("cp.async.cg.shared.global [%0], [%1], 16;" :: "r"(dst), "l"(src));
}
#define CP_COMMIT() asm volatile("cp.async.commit_group;" ::: "memory")
#define CP_WAIT(n)  asm volatile("cp.async.wait_group %0;" :: "n"(n) : "memory")

__device__ __forceinline__ void ldm4(uint32_t* r, uint32_t a) {
    asm volatile("ldmatrix.sync.aligned.m8n8.x4.shared.b16 {%0,%1,%2,%3}, [%4];"
        : "=r"(r[0]), "=r"(r[1]), "=r"(r[2]), "=r"(r[3]) : "r"(a));
}
__device__ __forceinline__ void mma16816(float* d, const uint32_t* a, const uint32_t* b) {
    asm volatile(
        "mma.sync.aligned.m16n8k16.row.col.f32.f16.f16.f32 "
        "{%0,%1,%2,%3}, {%4,%5,%6,%7}, {%8,%9}, {%0,%1,%2,%3};"
        : "+f"(d[0]), "+f"(d[1]), "+f"(d[2]), "+f"(d[3])
        : "r"(a[0]), "r"(a[1]), "r"(a[2]), "r"(a[3]), "r"(b[0]), "r"(b[1]));
}

// per-direction grid barrier: 64 blocks of direction d; xb = blockIdx.x
__device__ __forceinline__ void grid_barrier_dir(int d, int xb) {
    __syncthreads();
    if (threadIdx.x == 0) {
        __threadfence();
        unsigned gen = g_dgen[d][0];
        unsigned r = atomicAdd(&g_dcnt[d][xb & 3][0], 1u);
        bool released = false;
        if (r == 15) {
            unsigned r2 = atomicAdd(&g_dcnt2[d][0], 1u);
            if (r2 == 3) {
                g_dcnt[d][0][0] = 0; g_dcnt[d][1][0] = 0;
                g_dcnt[d][2][0] = 0; g_dcnt[d][3][0] = 0;
                g_dcnt2[d][0] = 0;
                __threadfence();
                g_dgen[d][0] = gen + 1;
                released = true;
            }
        }
        if (!released) { while (g_dgen[d][0] == gen) { } }
        __threadfence();
    }
    __syncthreads();
}

__device__ __forceinline__ void split_f16(float v, __half& hi, __half& lo) {
    hi = __float2half(v);
    lo = __float2half(v - __half2float(hi));
}
__device__ __forceinline__ float sigf(float v) { return 1.0f / (1.0f + __expf(-v)); }

// ---------------- conversion kernels ---------------------------------------
__global__ void conv_x_kernel(const float* __restrict__ x) {
    const size_t N = (size_t)MROWS * Hsz;
    for (size_t i = blockIdx.x * blockDim.x + threadIdx.x; i < N; i += (size_t)gridDim.x * blockDim.x) {
        int r = (int)(i >> 10), h = (int)(i & 1023);
        int b = r & 31, t = r >> 5;
        g_A16[0][i] = __float2half(x[((size_t)b * Tsz + t) * Hsz + h]);
    }
}

__global__ void conv_w_kernel(const float* __restrict__ Wf, const float* __restrict__ Wb, int layer) {
    const size_t N = (size_t)G4 * Hsz;
    for (size_t i = blockIdx.x * blockDim.x + threadIdx.x; i < 2 * N; i += (size_t)gridDim.x * blockDim.x) {
        int d = i >= N;
        size_t j = d ? i - N : i;
        float v = (d ? Wb : Wf)[(size_t)layer * N + j];
        __half hi, lo; split_f16(v, hi, lo);
        g_Wh16[d][j] = hi; g_Wl16[d][j] = lo;
    }
}

// Whh: fp16 + reorder rows: new row = x*64 + gate*16 + hl
__global__ void conv_rw_kernel(const float* __restrict__ Wf, const float* __restrict__ Wb, int layer) {
    const size_t N = (size_t)G4 * Hsz;
    for (size_t i = blockIdx.x * blockDim.x + threadIdx.x; i < 2 * N; i += (size_t)gridDim.x * blockDim.x) {
        int d = i >= N;
        size_t j = d ? i - N : i;
        int r = (int)(j >> 10), k = (int)(j & 1023);
        int g = r >> 10, h = r & 1023;
        int nr = (h >> 4) * 64 + g * 16 + (h & 15);
        g_Rh16[d][(size_t)nr * Hsz + k] = __float2half((d ? Wb : Wf)[(size_t)layer * N + j]);
    }
}

// ---------------- HMMA big input GEMM (fp16, 2 passes, KT=32, 3-stage) -----
__global__ void __launch_bounds__(256, 2) tc_gemm_kernel(
    const float* __restrict__ b_f, const float* __restrict__ b_b, int layer)
{
    extern __shared__ __align__(16) char sm[];
    const int d = blockIdx.z;
    const int mBlk = blockIdx.y * MT;
    const int nBlk = blockIdx.x * NT;
    const int tid = threadIdx.x, wid = tid >> 5, lid = tid & 31;

    const int aSel = (layer == 0) ? 0 : d;
    const __half* __restrict__ Aa = g_A16[aSel] + (size_t)mBlk * Hsz;
    const __half* __restrict__ Bh = g_Wh16[d] + (size_t)nBlk * Hsz;
    const __half* __restrict__ Bl = g_Wl16[d] + (size_t)nBlk * Hsz;
    const float* __restrict__ bias = (d == 0 ? b_f : b_b) + (size_t)layer * G4;

    const uint32_t smb = smem_u32(sm);

    const int lr0 = tid >> 2, lc0 = (tid & 3) * 8;
    const int lr1 = (tid + 256) >> 2;

    const int wm = wid & 1, wn = wid >> 1;
    const int ar = lid & 15, acg = lid >> 4;
    const int bnr = ((lid & 16) >> 1) | (lid & 7);
    const int bko = lid & 8;

    float acc[4][4][4] = {};

    auto issue_stage = [&](int st) {
        const int k0 = st * KT;
        const uint32_t base = smb + (st % 3) * STAGEB;
        uint32_t d0 = base + (uint32_t)(lr0 * KP + lc0) * 2;
        uint32_t d1 = base + (uint32_t)(lr1 * KP + lc0) * 2;
        size_t s0 = (size_t)lr0 * Hsz + k0 + lc0;
        size_t s1 = (size_t)lr1 * Hsz + k0 + lc0;
        cp16(d0 + 0 * BUFB, Aa + s0); cp16(d1 + 0 * BUFB, Aa + s1);
        cp16(d0 + 1 * BUFB, Bh + s0); cp16(d1 + 1 * BUFB, Bh + s1);
        cp16(d0 + 2 * BUFB, Bl + s0); cp16(d1 + 2 * BUFB, Bl + s1);
        CP_COMMIT();
    };

    issue_stage(0);
    issue_stage(1);

    const int NSTG = Hsz / KT; // 32
    for (int s = 0; s < NSTG; s++) {
        if (s + 2 < NSTG) {
            issue_stage(s + 2);
            CP_WAIT(2);
        } else if (s + 1 < NSTG) {
            CP_WAIT(1);
        } else {
            CP_WAIT(0);
        }
        __syncthreads();

        const uint32_t base = smb + (s % 3) * STAGEB;
#pragma unroll
        for (int kc = 0; kc < 2; kc++) {
            uint32_t ah[4][4], bh[2][4], bl[2][4];
#pragma unroll
            for (int mi = 0; mi < 4; mi++) {
                uint32_t ao = base + (uint32_t)((wm * 64 + mi * 16 + ar) * KP + kc * 16 + acg * 8) * 2;
                ldm4(ah[mi], ao);
            }
#pragma unroll
            for (int g = 0; g < 2; g++) {
                uint32_t bo = (uint32_t)((wn * 32 + g * 16 + bnr) * KP + kc * 16 + bko) * 2;
                ldm4(bh[g], base + BUFB + bo);
                ldm4(bl[g], base + 2 * BUFB + bo);
            }
#pragma unroll
            for (int mi = 0; mi < 4; mi++)
#pragma unroll
                for (int ni = 0; ni < 4; ni++)
                    mma16816(acc[mi][ni], ah[mi], &bh[ni >> 1][(ni & 1) * 2]);
#pragma unroll
            for (int mi = 0; mi < 4; mi++)
#pragma unroll
                for (int ni = 0; ni < 4; ni++)
                    mma16816(acc[mi][ni], ah[mi], &bl[ni >> 1][(ni & 1) * 2]);
        }
        __syncthreads();
    }

    const int er = lid >> 2, ec = (lid & 3) * 2;
#pragma unroll
    for (int mi = 0; mi < 4; mi++) {
#pragma unroll
        for (int ni = 0; ni < 4; ni++) {
            int gm = mBlk + wm * 64 + mi * 16 + er;
            int gn = nBlk + wn * 32 + ni * 8 + ec;
            float bv0 = bias[gn], bv1 = bias[gn + 1];
            float* p0 = g_G[d] + (size_t)gm * G4 + gn;
            p0[0] = acc[mi][ni][0] + bv0;
            p0[1] = acc[mi][ni][1] + bv1;
            float* p1 = p0 + (size_t)8 * G4;
            p1[0] = acc[mi][ni][2] + bv0;
            p1[1] = acc[mi][ni][3] + bv1;
        }
    }
}

// ---------------- persistent HMMA recurrent LSTM (fp16, single W pass) -----
// Grid (64, 2), 256 threads, 8 warps 2x4 (warp tile 16x16). Whh resident.
// A tiles pipelined (8 commit groups, incremental wait). Per-direction barrier.
__global__ void __launch_bounds__(256) lstm_hmma_kernel(
    int layer, float* __restrict__ outp, int extra)
{
    extern __shared__ __align__(16) char rsm[];
    const int x = blockIdx.x, d = blockIdx.y;
    const int tid = threadIdx.x, wid = tid >> 5, lid = tid & 31;
    const int wm = wid & 1, wn = wid >> 1;

    const uint32_t smb = smem_u32(rsm);
    float* gates_s = (float*)(rsm + OFF_GATES);
    float* c_s = (float*)(rsm + OFF_C);

    const __half* __restrict__ Bh = g_Rh16[d] + (size_t)(x * 64) * Hsz;

    // load maps
    const int arow = tid >> 3, ac2 = (tid & 7) * 2;   // A: 32 rows x 16 chunks
    const int brow = tid >> 2, bc4 = (tid & 3) * 4;   // B: 64 rows x 16 chunks

    // Resident Whh: 8 tiles of 64x128.
#pragma unroll
    for (int kt = 0; kt < 8; kt++) {
        uint32_t dst = smb + kt * R_TILEB + (uint32_t)(brow * RPB + bc4 * 16);
        const __half* src = Bh + (size_t)brow * Hsz + kt * 128 + bc4 * 8;
#pragma unroll
        for (int j = 0; j < 4; j++) cp16(dst + j * 16, src + j * 8);
    }
    CP_COMMIT();

    for (int i = tid; i < 512; i += 256) {
        int b = i >> 4, col = x * 16 + (i & 15);
        g_h16[0][d][b * Hsz + col] = __float2half(0.f);
        g_h16[1][d][b * Hsz + col] = __float2half(0.f);
        c_s[i] = 0.f;
    }
    CP_WAIT(0);
    grid_barrier_dir(d, x);

    // fragment maps
    const int ar = lid & 15, acg = lid >> 4;
    const int bnr = ((lid & 16) >> 1) | (lid & 7);
    const int bk8 = (lid & 8) >> 3;
    const uint32_t aRowOff = (uint32_t)((wm * 16 + ar) * RPB);
    const uint32_t bRowOff = (uint32_t)((wn * 16 + bnr) * RPB);

    // G prefetch map
    const int gb = tid >> 3, gseg = tid & 7;
    const uint32_t gdst = smb + OFF_GATES + (uint32_t)(gb * GATE_P + gseg * 8) * 4;
    const size_t goff0 = (size_t)(gseg >> 1) * 1024 + x * 16 + (gseg & 1) * 8;

    const uint32_t aOffT = (uint32_t)(arow * RPB + ac2 * 16);

    // pre-issue G for step 0
    {
        const int t0 = (d == 0) ? 0 : (Tsz - 1);
        cp16(gdst, g_G[d] + (size_t)(t0 * 32 + gb) * G4 + goff0);
        cp16(gdst + 16, g_G[d] + (size_t)(t0 * 32 + gb) * G4 + goff0 + 4);
        CP_COMMIT();
    }

    for (int s = 0; s < Tsz; s++) {
        const int p = s & 1;
        const int t = (d == 0) ? s : (Tsz - 1 - s);
        const __half* __restrict__ Ah = g_h16[p][d];

        // issue A tiles as 8 separate commit groups
#pragma unroll
        for (int kt = 0; kt < 8; kt++) {
            uint32_t dst = smb + OFF_A + kt * R_SA + aOffT;
            const __half* src = Ah + (size_t)arow * Hsz + kt * 128 + ac2 * 8;
            cp16(dst, src);
            cp16(dst + 16, src + 8);
            CP_COMMIT();
        }

        float accA[2][4] = {};

        // 8 phases; phase kt needs groups up through A_kt complete
#pragma unroll
        for (int kt = 0; kt < 8; kt++) {
            switch (kt) {
                case 0: CP_WAIT(7); break;
                case 1: CP_WAIT(6); break;
                case 2: CP_WAIT(5); break;
                case 3: CP_WAIT(4); break;
                case 4: CP_WAIT(3); break;
                case 5: CP_WAIT(2); break;
                case 6: CP_WAIT(1); break;
                default: CP_WAIT(0); break;
            }
            __syncthreads();
            const uint32_t stgA = smb + OFF_A + kt * R_SA;
            const uint32_t bres = smb + kt * R_TILEB;
#pragma unroll
            for (int kc = 0; kc < 8; kc++) {
                uint32_t ah[4], bh[4];
                ldm4(ah, stgA + aRowOff + (uint32_t)((kc * 2 + acg) * 16));
                ldm4(bh, bres + bRowOff + (uint32_t)((kc * 2 + bk8) * 16));
                mma16816(accA[0], ah, &bh[0]);
                mma16816(accA[1], ah, &bh[2]);
            }
        }

        // epilogue: gates_s (holds prefetched G) += acc (disjoint per warp)
        {
            const int er = lid >> 2, ec = (lid & 3) * 2;
            const int b0 = wm * 16 + er, b1 = b0 + 8;
#pragma unroll
            for (int ni = 0; ni < 2; ni++) {
                int col = wn * 16 + ni * 8 + ec;
                gates_s[b0 * GATE_P + col]     += accA[ni][0];
                gates_s[b0 * GATE_P + col + 1] += accA[ni][1];
                gates_s[b1 * GATE_P + col]     += accA[ni][2];
                gates_s[b1 * GATE_P + col + 1] += accA[ni][3];
            }
        }
        __syncthreads();

        // cell update: 2 (b, hl) pairs per thread
        const int np = p ^ 1;
        for (int i = tid; i < 512; i += 256) {
            int b = i >> 4, hl = i & 15;
            float gi = gates_s[b * GATE_P + 0 * 16 + hl];
            float gf = gates_s[b * GATE_P + 1 * 16 + hl];
            float gg = gates_s[b * GATE_P + 2 * 16 + hl];
            float go = gates_s[b * GATE_P + 3 * 16 + hl];
            float iv = sigf(gi), fv = sigf(gf), gv = tanhf(gg), ov = sigf(go);
            float cc = c_s[i];
            float cn = fv * cc + iv * gv;
            float hn = ov * tanhf(cn);
            c_s[i] = cn;

            int col = x * 16 + hl;
            g_h16[np][d][b * Hsz + col] = __float2half(hn);

            if (layer == 0) {
                g_A16[d][(size_t)(t * 32 + b) * Hsz + col] = __float2half(hn);
            } else {
                outp[((size_t)b * Tsz + t) * (2 * Hsz) + (size_t)d * Hsz + col] = hn;
                if (extra) {
                    outp[(size_t)Bsz * Tsz * 2 * Hsz + (size_t)d * Bsz * Tsz * Hsz
                         + ((size_t)b * Tsz + t) * Hsz + col] = hn;
                }
            }
        }
        __syncthreads();   // gates_s reads done before next step's G overwrite

        // pre-issue G for step s+1 (independent of h)
        if (s + 1 < Tsz) {
            const int tn = (d == 0) ? (s + 1) : (Tsz - 2 - s);
            cp16(gdst, g_G[d] + (size_t)(tn * 32 + gb) * G4 + goff0);
            cp16(gdst + 16, g_G[d] + (size_t)(tn * 32 + gb) * G4 + goff0 + 4);
            CP_COMMIT();
        }

        grid_barrier_dir(d, x);
    }
}

extern "C" void kernel_launch(void* const* d_in, const int* in_sizes, int n_in,
                              void* d_out, int out_size) {
    const float* x     = (const float*)d_in[0];
    const float* Wih_f = (const float*)d_in[1];
    const float* Whh_f = (const float*)d_in[2];
    const float* b_f   = (const float*)d_in[3];
    const float* Wih_b = (const float*)d_in[4];
    const float* Whh_b = (const float*)d_in[5];
    const float* b_b   = (const float*)d_in[6];
    float* out = (float*)d_out;

    const long long full = (long long)Bsz * Tsz * 4 * Hsz;
    int extra = ((long long)out_size >= full) ? 1 : 0;

    static int attr_done = 0;
    if (!attr_done) {
        cudaFuncSetAttribute(tc_gemm_kernel,
                             cudaFuncAttributeMaxDynamicSharedMemorySize, SMEM_GEMM);
        cudaFuncSetAttribute(lstm_hmma_kernel,
                             cudaFuncAttributeMaxDynamicSharedMemorySize, SMEM_R);
        attr_done = 1;
    }

    dim3 gemmGrid(G4 / NT, MROWS / MT, 2);   // (32, 128, 2)
    dim3 stepGrid(64, 2);                    // 128 co-resident blocks

    conv_x_kernel<<<2048, 256>>>(x);
    for (int layer = 0; layer < 2; layer++) {
        conv_w_kernel<<<2048, 256>>>(Wih_f, Wih_b, layer);
        conv_rw_kernel<<<2048, 256>>>(Whh_f, Whh_b, layer);
        tc_gemm_kernel<<<gemmGrid, 256, SMEM_GEMM>>>(b_f, b_b, layer);
        lstm_hmma_kernel<<<stepGrid, 256, SMEM_R>>>(layer, out, extra);
    }
}

// round 14
// speedup vs baseline: 1.1227x; 1.1227x over previous
#include <cuda_runtime.h>
#include <cuda_fp16.h>
#include <math.h>
#include <stdint.h>

// BiRNN (2-layer bidirectional LSTM), B=32, T=512, H=1024.
// Round 14: input GEMM drops the W_lo pass (all weights single fp16) —
// GEMM MMA work halves. Round-12 two-stage GEMM structure; recurrent
// unchanged from round 13 (per-direction barrier, pipelined A tiles).

#define Bsz 32
#define Tsz 512
#define Hsz 1024
#define G4  4096
#define MROWS (Tsz * Bsz) // 16384

// big input GEMM tiling (two-stage, single W pass)
#define MT 128
#define NT 128
#define KT 32
#define KP 40                     // smem pitch in fp16 (80B)
#define BUFB (MT * KP * 2)        // 10240
#define STAGEB (2 * BUFB)         // A, W = 20480
#define SMEM_GEMM (2 * STAGEB)    // 40960

// recurrent tiling: K-tile 128 fp16 (256B) padded to 272B pitch
#define RPB 272
#define R_SA (32 * RPB)                 // 8704  (one A tile)
#define R_TILEB (64 * RPB)              // 17408 (one B tile)
#define R_RES (8 * R_TILEB)             // resident Whh: 139264
#define OFF_A R_RES                     // full A: 8 tiles
#define OFF_GATES (OFF_A + 8 * R_SA)    // 208896
#define GATE_P 68
#define OFF_C (OFF_GATES + 32 * GATE_P * 4) // 217600
#define SMEM_R (OFF_C + 2048)               // 219648

// ---------------- device globals -------------------------------------------
__device__ float g_G[2][(size_t)MROWS * G4];                 // x-part gates + bias
__device__ __align__(256) __half g_A16[2][(size_t)MROWS * Hsz];   // activations fp16
__device__ __align__(256) __half g_Wh16[2][(size_t)G4 * Hsz];     // Wih fp16
__device__ __align__(256) __half g_Rh16[2][(size_t)G4 * Hsz];     // Whh fp16 (reordered)
__device__ __align__(256) __half g_h16[2][2][Bsz * Hsz];          // [parity][dir]
// per-direction barrier state (padded)
__device__ unsigned g_dcnt[2][4][64];
__device__ unsigned g_dcnt2[2][64];
__device__ volatile unsigned g_dgen[2][64];

// ---------------- helpers ---------------------------------------------------
__device__ __forceinline__ uint32_t smem_u32(const void* p) {
    uint32_t a;
    asm("{ .reg .u64 t; cvta.to.shared.u64 t, %1; cvt.u32.u64 %0, t; }" : "=r"(a) : "l"(p));
    return a;
}
__device__ __forceinline__ void cp16(uint32_t dst, const void* src) {
    asm volatile("cp.async.cg.shared.global [%0], [%1], 16;" :: "r"(dst), "l"(src));
}
#define CP_COMMIT() asm volatile("cp.async.commit_group;" ::: "memory")
#define CP_WAIT(n)  asm volatile("cp.async.wait_group %0;" :: "n"(n) : "memory")

__device__ __forceinline__ void ldm4(uint32_t* r, uint32_t a) {
    asm volatile("ldmatrix.sync.aligned.m8n8.x4.shared.b16 {%0,%1,%2,%3}, [%4];"
        : "=r"(r[0]), "=r"(r[1]), "=r"(r[2]), "=r"(r[3]) : "r"(a));
}
__device__ __forceinline__ void mma16816(float* d, const uint32_t* a, const uint32_t* b) {
    asm volatile(
        "mma.sync.aligned.m16n8k16.row.col.f32.f16.f16.f32 "
        "{%0,%1,%2,%3}, {%4,%5,%6,%7}, {%8,%9}, {%0,%1,%2,%3};"
        : "+f"(d[0]), "+f"(d[1]), "+f"(d[2]), "+f"(d[3])
        : "r"(a[0]), "r"(a[1]), "r"(a[2]), "r"(a[3]), "r"(b[0]), "r"(b[1]));
}

// per-direction grid barrier: 64 blocks of direction d
__device__ __forceinline__ void grid_barrier_dir(int d, int xb) {
    __syncthreads();
    if (threadIdx.x == 0) {
        __threadfence();
        unsigned gen = g_dgen[d][0];
        unsigned r = atomicAdd(&g_dcnt[d][xb & 3][0], 1u);
        bool released = false;
        if (r == 15) {
            unsigned r2 = atomicAdd(&g_dcnt2[d][0], 1u);
            if (r2 == 3) {
                g_dcnt[d][0][0] = 0; g_dcnt[d][1][0] = 0;
                g_dcnt[d][2][0] = 0; g_dcnt[d][3][0] = 0;
                g_dcnt2[d][0] = 0;
                __threadfence();
                g_dgen[d][0] = gen + 1;
                released = true;
            }
        }
        if (!released) { while (g_dgen[d][0] == gen) { } }
        __threadfence();
    }
    __syncthreads();
}

__device__ __forceinline__ float sigf(float v) { return 1.0f / (1.0f + __expf(-v)); }

// ---------------- conversion kernels ---------------------------------------
__global__ void conv_x_kernel(const float* __restrict__ x) {
    const size_t N = (size_t)MROWS * Hsz;
    for (size_t i = blockIdx.x * blockDim.x + threadIdx.x; i < N; i += (size_t)gridDim.x * blockDim.x) {
        int r = (int)(i >> 10), h = (int)(i & 1023);
        int b = r & 31, t = r >> 5;
        g_A16[0][i] = __float2half(x[((size_t)b * Tsz + t) * Hsz + h]);
    }
}

__global__ void conv_w_kernel(const float* __restrict__ Wf, const float* __restrict__ Wb, int layer) {
    const size_t N = (size_t)G4 * Hsz;
    for (size_t i = blockIdx.x * blockDim.x + threadIdx.x; i < 2 * N; i += (size_t)gridDim.x * blockDim.x) {
        int d = i >= N;
        size_t j = d ? i - N : i;
        g_Wh16[d][j] = __float2half((d ? Wb : Wf)[(size_t)layer * N + j]);
    }
}

// Whh: fp16 + reorder rows: new row = x*64 + gate*16 + hl
__global__ void conv_rw_kernel(const float* __restrict__ Wf, const float* __restrict__ Wb, int layer) {
    const size_t N = (size_t)G4 * Hsz;
    for (size_t i = blockIdx.x * blockDim.x + threadIdx.x; i < 2 * N; i += (size_t)gridDim.x * blockDim.x) {
        int d = i >= N;
        size_t j = d ? i - N : i;
        int r = (int)(j >> 10), k = (int)(j & 1023);
        int g = r >> 10, h = r & 1023;
        int nr = (h >> 4) * 64 + g * 16 + (h & 15);
        g_Rh16[d][(size_t)nr * Hsz + k] = __float2half((d ? Wb : Wf)[(size_t)layer * N + j]);
    }
}

// ---------------- HMMA big input GEMM (fp16, 1 pass, KT=32, 2-stage) -------
__global__ void __launch_bounds__(256, 2) tc_gemm_kernel(
    const float* __restrict__ b_f, const float* __restrict__ b_b, int layer)
{
    extern __shared__ __align__(16) char sm[];
    const int d = blockIdx.z;
    const int mBlk = blockIdx.y * MT;
    const int nBlk = blockIdx.x * NT;
    const int tid = threadIdx.x, wid = tid >> 5, lid = tid & 31;

    const int aSel = (layer == 0) ? 0 : d;
    const __half* __restrict__ Aa = g_A16[aSel] + (size_t)mBlk * Hsz;
    const __half* __restrict__ Bw = g_Wh16[d] + (size_t)nBlk * Hsz;
    const float* __restrict__ bias = (d == 0 ? b_f : b_b) + (size_t)layer * G4;

    const uint32_t smb = smem_u32(sm);

    const int lr0 = tid >> 2, lc0 = (tid & 3) * 8;
    const int lr1 = (tid + 256) >> 2;

    const int wm = wid & 1, wn = wid >> 1;
    const int ar = lid & 15, acg = lid >> 4;
    const int bnr = ((lid & 16) >> 1) | (lid & 7);
    const int bko = lid & 8;

    float acc[4][4][4] = {};

    {
        const uint32_t base = smb;
        uint32_t d0 = base + (uint32_t)(lr0 * KP + lc0) * 2;
        uint32_t d1 = base + (uint32_t)(lr1 * KP + lc0) * 2;
        size_t s0 = (size_t)lr0 * Hsz + lc0;
        size_t s1 = (size_t)lr1 * Hsz + lc0;
        cp16(d0 + 0 * BUFB, Aa + s0); cp16(d1 + 0 * BUFB, Aa + s1);
        cp16(d0 + 1 * BUFB, Bw + s0); cp16(d1 + 1 * BUFB, Bw + s1);
        CP_COMMIT();
    }

    const int NSTG = Hsz / KT; // 32
    for (int s = 0; s < NSTG; s++) {
        if (s + 1 < NSTG) {
            const int k0 = (s + 1) * KT;
            const uint32_t base = smb + ((s + 1) & 1) * STAGEB;
            uint32_t d0 = base + (uint32_t)(lr0 * KP + lc0) * 2;
            uint32_t d1 = base + (uint32_t)(lr1 * KP + lc0) * 2;
            size_t s0 = (size_t)lr0 * Hsz + k0 + lc0;
            size_t s1 = (size_t)lr1 * Hsz + k0 + lc0;
            cp16(d0 + 0 * BUFB, Aa + s0); cp16(d1 + 0 * BUFB, Aa + s1);
            cp16(d0 + 1 * BUFB, Bw + s0); cp16(d1 + 1 * BUFB, Bw + s1);
            CP_COMMIT();
            CP_WAIT(1);
        } else {
            CP_WAIT(0);
        }
        __syncthreads();

        const uint32_t base = smb + (s & 1) * STAGEB;
#pragma unroll
        for (int kc = 0; kc < 2; kc++) {
            uint32_t ah[4][4], bh[2][4];
#pragma unroll
            for (int mi = 0; mi < 4; mi++) {
                uint32_t ao = base + (uint32_t)((wm * 64 + mi * 16 + ar) * KP + kc * 16 + acg * 8) * 2;
                ldm4(ah[mi], ao);
            }
#pragma unroll
            for (int g = 0; g < 2; g++) {
                uint32_t bo = (uint32_t)((wn * 32 + g * 16 + bnr) * KP + kc * 16 + bko) * 2;
                ldm4(bh[g], base + BUFB + bo);
            }
#pragma unroll
            for (int mi = 0; mi < 4; mi++)
#pragma unroll
                for (int ni = 0; ni < 4; ni++)
                    mma16816(acc[mi][ni], ah[mi], &bh[ni >> 1][(ni & 1) * 2]);
        }
        __syncthreads();
    }

    const int er = lid >> 2, ec = (lid & 3) * 2;
#pragma unroll
    for (int mi = 0; mi < 4; mi++) {
#pragma unroll
        for (int ni = 0; ni < 4; ni++) {
            int gm = mBlk + wm * 64 + mi * 16 + er;
            int gn = nBlk + wn * 32 + ni * 8 + ec;
            float bv0 = bias[gn], bv1 = bias[gn + 1];
            float* p0 = g_G[d] + (size_t)gm * G4 + gn;
            p0[0] = acc[mi][ni][0] + bv0;
            p0[1] = acc[mi][ni][1] + bv1;
            float* p1 = p0 + (size_t)8 * G4;
            p1[0] = acc[mi][ni][2] + bv0;
            p1[1] = acc[mi][ni][3] + bv1;
        }
    }
}

// ---------------- persistent HMMA recurrent LSTM (fp16, single W pass) -----
// Grid (64, 2), 256 threads, 8 warps 2x4 (warp tile 16x16). Whh resident.
// A tiles pipelined (8 commit groups, incremental wait). Per-direction barrier.
__global__ void __launch_bounds__(256) lstm_hmma_kernel(
    int layer, float* __restrict__ outp, int extra)
{
    extern __shared__ __align__(16) char rsm[];
    const int x = blockIdx.x, d = blockIdx.y;
    const int tid = threadIdx.x, wid = tid >> 5, lid = tid & 31;
    const int wm = wid & 1, wn = wid >> 1;

    const uint32_t smb = smem_u32(rsm);
    float* gates_s = (float*)(rsm + OFF_GATES);
    float* c_s = (float*)(rsm + OFF_C);

    const __half* __restrict__ Bh = g_Rh16[d] + (size_t)(x * 64) * Hsz;

    const int arow = tid >> 3, ac2 = (tid & 7) * 2;
    const int brow = tid >> 2, bc4 = (tid & 3) * 4;

    // Resident Whh: 8 tiles of 64x128.
#pragma unroll
    for (int kt = 0; kt < 8; kt++) {
        uint32_t dst = smb + kt * R_TILEB + (uint32_t)(brow * RPB + bc4 * 16);
        const __half* src = Bh + (size_t)brow * Hsz + kt * 128 + bc4 * 8;
#pragma unroll
        for (int j = 0; j < 4; j++) cp16(dst + j * 16, src + j * 8);
    }
    CP_COMMIT();

    for (int i = tid; i < 512; i += 256) {
        int b = i >> 4, col = x * 16 + (i & 15);
        g_h16[0][d][b * Hsz + col] = __float2half(0.f);
        g_h16[1][d][b * Hsz + col] = __float2half(0.f);
        c_s[i] = 0.f;
    }
    CP_WAIT(0);
    grid_barrier_dir(d, x);

    const int ar = lid & 15, acg = lid >> 4;
    const int bnr = ((lid & 16) >> 1) | (lid & 7);
    const int bk8 = (lid & 8) >> 3;
    const uint32_t aRowOff = (uint32_t)((wm * 16 + ar) * RPB);
    const uint32_t bRowOff = (uint32_t)((wn * 16 + bnr) * RPB);

    const int gb = tid >> 3, gseg = tid & 7;
    const uint32_t gdst = smb + OFF_GATES + (uint32_t)(gb * GATE_P + gseg * 8) * 4;
    const size_t goff0 = (size_t)(gseg >> 1) * 1024 + x * 16 + (gseg & 1) * 8;

    const uint32_t aOffT = (uint32_t)(arow * RPB + ac2 * 16);

    // pre-issue G for step 0
    {
        const int t0 = (d == 0) ? 0 : (Tsz - 1);
        cp16(gdst, g_G[d] + (size_t)(t0 * 32 + gb) * G4 + goff0);
        cp16(gdst + 16, g_G[d] + (size_t)(t0 * 32 + gb) * G4 + goff0 + 4);
        CP_COMMIT();
    }

    for (int s = 0; s < Tsz; s++) {
        const int p = s & 1;
        const int t = (d == 0) ? s : (Tsz - 1 - s);
        const __half* __restrict__ Ah = g_h16[p][d];

        // issue A tiles as 8 separate commit groups
#pragma unroll
        for (int kt = 0; kt < 8; kt++) {
            uint32_t dst = smb + OFF_A + kt * R_SA + aOffT;
            const __half* src = Ah + (size_t)arow * Hsz + kt * 128 + ac2 * 8;
            cp16(dst, src);
            cp16(dst + 16, src + 8);
            CP_COMMIT();
        }

        float accA[2][4] = {};

#pragma unroll
        for (int kt = 0; kt < 8; kt++) {
            switch (kt) {
                case 0: CP_WAIT(7); break;
                case 1: CP_WAIT(6); break;
                case 2: CP_WAIT(5); break;
                case 3: CP_WAIT(4); break;
                case 4: CP_WAIT(3); break;
                case 5: CP_WAIT(2); break;
                case 6: CP_WAIT(1); break;
                default: CP_WAIT(0); break;
            }
            __syncthreads();
            const uint32_t stgA = smb + OFF_A + kt * R_SA;
            const uint32_t bres = smb + kt * R_TILEB;
#pragma unroll
            for (int kc = 0; kc < 8; kc++) {
                uint32_t ah[4], bh[4];
                ldm4(ah, stgA + aRowOff + (uint32_t)((kc * 2 + acg) * 16));
                ldm4(bh, bres + bRowOff + (uint32_t)((kc * 2 + bk8) * 16));
                mma16816(accA[0], ah, &bh[0]);
                mma16816(accA[1], ah, &bh[2]);
            }
        }

        // epilogue: gates_s (holds prefetched G) += acc (disjoint per warp)
        {
            const int er = lid >> 2, ec = (lid & 3) * 2;
            const int b0 = wm * 16 + er, b1 = b0 + 8;
#pragma unroll
            for (int ni = 0; ni < 2; ni++) {
                int col = wn * 16 + ni * 8 + ec;
                gates_s[b0 * GATE_P + col]     += accA[ni][0];
                gates_s[b0 * GATE_P + col + 1] += accA[ni][1];
                gates_s[b1 * GATE_P + col]     += accA[ni][2];
                gates_s[b1 * GATE_P + col + 1] += accA[ni][3];
            }
        }
        __syncthreads();

        // cell update: 2 (b, hl) pairs per thread
        const int np = p ^ 1;
        for (int i = tid; i < 512; i += 256) {
            int b = i >> 4, hl = i & 15;
            float gi = gates_s[b * GATE_P + 0 * 16 + hl];
            float gf = gates_s[b * GATE_P + 1 * 16 + hl];
            float gg = gates_s[b * GATE_P + 2 * 16 + hl];
            float go = gates_s[b * GATE_P + 3 * 16 + hl];
            float iv = sigf(gi), fv = sigf(gf), gv = tanhf(gg), ov = sigf(go);
            float cc = c_s[i];
            float cn = fv * cc + iv * gv;
            float hn = ov * tanhf(cn);
            c_s[i] = cn;

            int col = x * 16 + hl;
            g_h16[np][d][b * Hsz + col] = __float2half(hn);

            if (layer == 0) {
                g_A16[d][(size_t)(t * 32 + b) * Hsz + col] = __float2half(hn);
            } else {
                outp[((size_t)b * Tsz + t) * (2 * Hsz) + (size_t)d * Hsz + col] = hn;
                if (extra) {
                    outp[(size_t)Bsz * Tsz * 2 * Hsz + (size_t)d * Bsz * Tsz * Hsz
                         + ((size_t)b * Tsz + t) * Hsz + col] = hn;
                }
            }
        }
        __syncthreads();   // gates_s reads done before next step's G overwrite

        // pre-issue G for step s+1 (independent of h)
        if (s + 1 < Tsz) {
            const int tn = (d == 0) ? (s + 1) : (Tsz - 2 - s);
            cp16(gdst, g_G[d] + (size_t)(tn * 32 + gb) * G4 + goff0);
            cp16(gdst + 16, g_G[d] + (size_t)(tn * 32 + gb) * G4 + goff0 + 4);
            CP_COMMIT();
        }

        grid_barrier_dir(d, x);
    }
}

extern "C" void kernel_launch(void* const* d_in, const int* in_sizes, int n_in,
                              void* d_out, int out_size) {
    const float* x     = (const float*)d_in[0];
    const float* Wih_f = (const float*)d_in[1];
    const float* Whh_f = (const float*)d_in[2];
    const float* b_f   = (const float*)d_in[3];
    const float* Wih_b = (const float*)d_in[4];
    const float* Whh_b = (const float*)d_in[5];
    const float* b_b   = (const float*)d_in[6];
    float* out = (float*)d_out;

    const long long full = (long long)Bsz * Tsz * 4 * Hsz;
    int extra = ((long long)out_size >= full) ? 1 : 0;

    static int attr_done = 0;
    if (!attr_done) {
        cudaFuncSetAttribute(tc_gemm_kernel,
                             cudaFuncAttributeMaxDynamicSharedMemorySize, SMEM_GEMM);
        cudaFuncSetAttribute(lstm_hmma_kernel,
                             cudaFuncAttributeMaxDynamicSharedMemorySize, SMEM_R);
        attr_done = 1;
    }

    dim3 gemmGrid(G4 / NT, MROWS / MT, 2);   // (32, 128, 2)
    dim3 stepGrid(64, 2);                    // 128 co-resident blocks

    conv_x_kernel<<<2048, 256>>>(x);
    for (int layer = 0; layer < 2; layer++) {
        conv_w_kernel<<<2048, 256>>>(Wih_f, Wih_b, layer);
        conv_rw_kernel<<<2048, 256>>>(Whh_f, Whh_b, layer);
        tc_gemm_kernel<<<gemmGrid, 256, SMEM_GEMM>>>(b_f, b_b, layer);
        lstm_hmma_kernel<<<stepGrid, 256, SMEM_R>>>(layer, out, extra);
    }
}

// round 16
// speedup vs baseline: 1.1507x; 1.0250x over previous
#include <cuda_runtime.h>
#include <cuda_fp16.h>
#include <math.h>
#include <stdint.h>

// BiRNN (2-layer bidirectional LSTM), B=32, T=512, H=1024.
// Round 15: recurrent kernel -> 512 threads / 16 warps, 2-way K-split
// (per-half named barriers, separate gate accum buffers) to overlap the
// tensor pipe with the smem crossbar. GEMM unchanged from round 14.

#define Bsz 32
#define Tsz 512
#define Hsz 1024
#define G4  4096
#define MROWS (Tsz * Bsz) // 16384

// big input GEMM tiling (two-stage, single W pass) — round-14 proven
#define MT 128
#define NT 128
#define KT 32
#define KP 40
#define BUFB (MT * KP * 2)        // 10240
#define STAGEB (2 * BUFB)         // A, W = 20480
#define SMEM_GEMM (2 * STAGEB)    // 40960

// recurrent tiling: K-tile 128 fp16 (256B) padded to 272B pitch
#define RPB 272
#define R_SA (32 * RPB)                 // 8704  (one A tile)
#define R_TILEB (64 * RPB)              // 17408 (one B tile)
#define R_RES (8 * R_TILEB)             // resident Whh: 139264
#define OFF_A R_RES                     // full A: 8 tiles
#define OFF_GATES (OFF_A + 8 * R_SA)    // 208896
#define GATE_P 68
#define OFF_C (OFF_GATES + 32 * GATE_P * 4) // 217600
#define OFF_G2 (OFF_C + 2048)               // 219648 (second gate buffer)
#define SMEM_R (OFF_G2 + 32 * GATE_P * 4)   // 228352

// ---------------- device globals -------------------------------------------
__device__ float g_G[2][(size_t)MROWS * G4];                 // x-part gates + bias
__device__ __align__(256) __half g_A16[2][(size_t)MROWS * Hsz];   // activations fp16
__device__ __align__(256) __half g_Wh16[2][(size_t)G4 * Hsz];     // Wih fp16
__device__ __align__(256) __half g_Rh16[2][(size_t)G4 * Hsz];     // Whh fp16 (reordered)
__device__ __align__(256) __half g_h16[2][2][Bsz * Hsz];          // [parity][dir]
// per-direction barrier state (padded)
__device__ unsigned g_dcnt[2][4][64];
__device__ unsigned g_dcnt2[2][64];
__device__ volatile unsigned g_dgen[2][64];

// ---------------- helpers ---------------------------------------------------
__device__ __forceinline__ uint32_t smem_u32(const void* p) {
    uint32_t a;
    asm("{ .reg .u64 t; cvta.to.shared.u64 t, %1; cvt.u32.u64 %0, t; }" : "=r"(a) : "l"(p));
    return a;
}
__device__ __forceinline__ void cp16(uint32_t dst, const void* src) {
    asm volatile("cp.async.cg.shared.global [%0], [%1], 16;" :: "r"(dst), "l"(src));
}
#define CP_COMMIT() asm volatile("cp.async.commit_group;" ::: "memory")
#define CP_WAIT(n)  asm volatile("cp.async.wait_group %0;" :: "n"(n) : "memory")
#define BAR_SYNC(id, cnt) asm volatile("bar.sync %0, %1;" :: "r"(id), "r"(cnt) : "memory")

__device__ __forceinline__ void ldm4(uint32_t* r, uint32_t a) {
    asm volatile("ldmatrix.sync.aligned.m8n8.x4.shared.b16 {%0,%1,%2,%3}, [%4];"
        : "=r"(r[0]), "=r"(r[1]), "=r"(r[2]), "=r"(r[3]) : "r"(a));
}
__device__ __forceinline__ void mma16816(float* d, const uint32_t* a, const uint32_t* b) {
    asm volatile(
        "mma.sync.aligned.m16n8k16.row.col.f32.f16.f16.f32 "
        "{%0,%1,%2,%3}, {%4,%5,%6,%7}, {%8,%9}, {%0,%1,%2,%3};"
        : "+f"(d[0]), "+f"(d[1]), "+f"(d[2]), "+f"(d[3])
        : "r"(a[0]), "r"(a[1]), "r"(a[2]), "r"(a[3]), "r"(b[0]), "r"(b[1]));
}

// per-direction grid barrier: 64 blocks of direction d
__device__ __forceinline__ void grid_barrier_dir(int d, int xb) {
    __syncthreads();
    if (threadIdx.x == 0) {
        __threadfence();
        unsigned gen = g_dgen[d][0];
        unsigned r = atomicAdd(&g_dcnt[d][xb & 3][0], 1u);
        bool released = false;
        if (r == 15) {
            unsigned r2 = atomicAdd(&g_dcnt2[d][0], 1u);
            if (r2 == 3) {
                g_dcnt[d][0][0] = 0; g_dcnt[d][1][0] = 0;
                g_dcnt[d][2][0] = 0; g_dcnt[d][3][0] = 0;
                g_dcnt2[d][0] = 0;
                __threadfence();
                g_dgen[d][0] = gen + 1;
                released = true;
            }
        }
        if (!released) { while (g_dgen[d][0] == gen) { } }
        __threadfence();
    }
    __syncthreads();
}

__device__ __forceinline__ float sigf(float v) { return 1.0f / (1.0f + __expf(-v)); }

// ---------------- conversion kernels ---------------------------------------
__global__ void conv_x_kernel(const float* __restrict__ x) {
    const size_t N = (size_t)MROWS * Hsz;
    for (size_t i = blockIdx.x * blockDim.x + threadIdx.x; i < N; i += (size_t)gridDim.x * blockDim.x) {
        int r = (int)(i >> 10), h = (int)(i & 1023);
        int b = r & 31, t = r >> 5;
        g_A16[0][i] = __float2half(x[((size_t)b * Tsz + t) * Hsz + h]);
    }
}

__global__ void conv_w_kernel(const float* __restrict__ Wf, const float* __restrict__ Wb, int layer) {
    const size_t N = (size_t)G4 * Hsz;
    for (size_t i = blockIdx.x * blockDim.x + threadIdx.x; i < 2 * N; i += (size_t)gridDim.x * blockDim.x) {
        int d = i >= N;
        size_t j = d ? i - N : i;
        g_Wh16[d][j] = __float2half((d ? Wb : Wf)[(size_t)layer * N + j]);
    }
}

// Whh: fp16 + reorder rows: new row = x*64 + gate*16 + hl
__global__ void conv_rw_kernel(const float* __restrict__ Wf, const float* __restrict__ Wb, int layer) {
    const size_t N = (size_t)G4 * Hsz;
    for (size_t i = blockIdx.x * blockDim.x + threadIdx.x; i < 2 * N; i += (size_t)gridDim.x * blockDim.x) {
        int d = i >= N;
        size_t j = d ? i - N : i;
        int r = (int)(j >> 10), k = (int)(j & 1023);
        int g = r >> 10, h = r & 1023;
        int nr = (h >> 4) * 64 + g * 16 + (h & 15);
        g_Rh16[d][(size_t)nr * Hsz + k] = __float2half((d ? Wb : Wf)[(size_t)layer * N + j]);
    }
}

// ---------------- HMMA big input GEMM (fp16, 1 pass, KT=32, 2-stage) -------
__global__ void __launch_bounds__(256, 2) tc_gemm_kernel(
    const float* __restrict__ b_f, const float* __restrict__ b_b, int layer)
{
    extern __shared__ __align__(16) char sm[];
    const int d = blockIdx.z;
    const int mBlk = blockIdx.y * MT;
    const int nBlk = blockIdx.x * NT;
    const int tid = threadIdx.x, wid = tid >> 5, lid = tid & 31;

    const int aSel = (layer == 0) ? 0 : d;
    const __half* __restrict__ Aa = g_A16[aSel] + (size_t)mBlk * Hsz;
    const __half* __restrict__ Bw = g_Wh16[d] + (size_t)nBlk * Hsz;
    const float* __restrict__ bias = (d == 0 ? b_f : b_b) + (size_t)layer * G4;

    const uint32_t smb = smem_u32(sm);

    const int lr0 = tid >> 2, lc0 = (tid & 3) * 8;
    const int lr1 = (tid + 256) >> 2;

    const int wm = wid & 1, wn = wid >> 1;
    const int ar = lid & 15, acg = lid >> 4;
    const int bnr = ((lid & 16) >> 1) | (lid & 7);
    const int bko = lid & 8;

    float acc[4][4][4] = {};

    {
        const uint32_t base = smb;
        uint32_t d0 = base + (uint32_t)(lr0 * KP + lc0) * 2;
        uint32_t d1 = base + (uint32_t)(lr1 * KP + lc0) * 2;
        size_t s0 = (size_t)lr0 * Hsz + lc0;
        size_t s1 = (size_t)lr1 * Hsz + lc0;
        cp16(d0 + 0 * BUFB, Aa + s0); cp16(d1 + 0 * BUFB, Aa + s1);
        cp16(d0 + 1 * BUFB, Bw + s0); cp16(d1 + 1 * BUFB, Bw + s1);
        CP_COMMIT();
    }

    const int NSTG = Hsz / KT; // 32
    for (int s = 0; s < NSTG; s++) {
        if (s + 1 < NSTG) {
            const int k0 = (s + 1) * KT;
            const uint32_t base = smb + ((s + 1) & 1) * STAGEB;
            uint32_t d0 = base + (uint32_t)(lr0 * KP + lc0) * 2;
            uint32_t d1 = base + (uint32_t)(lr1 * KP + lc0) * 2;
            size_t s0 = (size_t)lr0 * Hsz + k0 + lc0;
            size_t s1 = (size_t)lr1 * Hsz + k0 + lc0;
            cp16(d0 + 0 * BUFB, Aa + s0); cp16(d1 + 0 * BUFB, Aa + s1);
            cp16(d0 + 1 * BUFB, Bw + s0); cp16(d1 + 1 * BUFB, Bw + s1);
            CP_COMMIT();
            CP_WAIT(1);
        } else {
            CP_WAIT(0);
        }
        __syncthreads();

        const uint32_t base = smb + (s & 1) * STAGEB;
#pragma unroll
        for (int kc = 0; kc < 2; kc++) {
            uint32_t ah[4][4], bh[2][4];
#pragma unroll
            for (int mi = 0; mi < 4; mi++) {
                uint32_t ao = base + (uint32_t)((wm * 64 + mi * 16 + ar) * KP + kc * 16 + acg * 8) * 2;
                ldm4(ah[mi], ao);
            }
#pragma unroll
            for (int g = 0; g < 2; g++) {
                uint32_t bo = (uint32_t)((wn * 32 + g * 16 + bnr) * KP + kc * 16 + bko) * 2;
                ldm4(bh[g], base + BUFB + bo);
            }
#pragma unroll
            for (int mi = 0; mi < 4; mi++)
#pragma unroll
                for (int ni = 0; ni < 4; ni++)
                    mma16816(acc[mi][ni], ah[mi], &bh[ni >> 1][(ni & 1) * 2]);
        }
        __syncthreads();
    }

    const int er = lid >> 2, ec = (lid & 3) * 2;
#pragma unroll
    for (int mi = 0; mi < 4; mi++) {
#pragma unroll
        for (int ni = 0; ni < 4; ni++) {
            int gm = mBlk + wm * 64 + mi * 16 + er;
            int gn = nBlk + wn * 32 + ni * 8 + ec;
            float bv0 = bias[gn], bv1 = bias[gn + 1];
            float* p0 = g_G[d] + (size_t)gm * G4 + gn;
            p0[0] = acc[mi][ni][0] + bv0;
            p0[1] = acc[mi][ni][1] + bv1;
            float* p1 = p0 + (size_t)8 * G4;
            p1[0] = acc[mi][ni][2] + bv0;
            p1[1] = acc[mi][ni][3] + bv1;
        }
    }
}

// ---------------- persistent HMMA recurrent LSTM (fp16, 16 warps) ----------
// Grid (64, 2), 512 threads. Warp layout: wk = wid>>3 (K half), wm, wn.
// Each half loads its 4 A tiles and syncs with its own named barrier.
// Half 0 accumulates into gates_s (+= over prefetched G); half 1 stores
// into gates2_s; cell update sums both.
__global__ void __launch_bounds__(512) lstm_hmma_kernel(
    int layer, float* __restrict__ outp, int extra)
{
    extern __shared__ __align__(16) char rsm[];
    const int x = blockIdx.x, d = blockIdx.y;
    const int tid = threadIdx.x, wid = tid >> 5, lid = tid & 31;
    const int wk = wid >> 3;                 // K half 0/1
    const int wrem = wid & 7;
    const int wm = wrem & 1, wn = wrem >> 1; // 2 x 4 within half

    const uint32_t smb = smem_u32(rsm);
    float* gates_s  = (float*)(rsm + OFF_GATES);
    float* c_s      = (float*)(rsm + OFF_C);
    float* gates2_s = (float*)(rsm + OFF_G2);

    const __half* __restrict__ Bh = g_Rh16[d] + (size_t)(x * 64) * Hsz;

    // Resident Whh: 8 tiles of 64x128; 512 threads, 2 chunks per tile each.
    {
        const int brow = tid >> 3, bc2 = (tid & 7) * 2;
#pragma unroll
        for (int kt = 0; kt < 8; kt++) {
            uint32_t dst = smb + kt * R_TILEB + (uint32_t)(brow * RPB + bc2 * 16);
            const __half* src = Bh + (size_t)brow * Hsz + kt * 128 + bc2 * 8;
            cp16(dst, src);
            cp16(dst + 16, src + 8);
        }
        CP_COMMIT();
    }

    {
        int b = tid >> 4, col = x * 16 + (tid & 15);
        g_h16[0][d][b * Hsz + col] = __float2half(0.f);
        g_h16[1][d][b * Hsz + col] = __float2half(0.f);
        c_s[tid] = 0.f;
    }
    CP_WAIT(0);
    grid_barrier_dir(d, x);

    // fragment maps
    const int ar = lid & 15, acg = lid >> 4;
    const int bnr = ((lid & 16) >> 1) | (lid & 7);
    const int bk8 = (lid & 8) >> 3;
    const uint32_t aRowOff = (uint32_t)((wm * 16 + ar) * RPB);
    const uint32_t bRowOff = (uint32_t)((wn * 16 + bnr) * RPB);

    // A load map (per half: 256 contiguous threads)
    const int h255 = tid & 255;
    const int arow = h255 >> 3, ac2 = (h255 & 7) * 2;
    const uint32_t aOffT = (uint32_t)(arow * RPB + ac2 * 16);

    // G prefetch map: 512 threads x 1 cp16 = 2048 floats
    const int gb = tid >> 4, gch = tid & 15;
    const uint32_t gdst = smb + OFF_GATES + (uint32_t)(gb * GATE_P + gch * 4) * 4;
    const size_t goff0 = (size_t)(gch >> 2) * 1024 + x * 16 + (gch & 3) * 4;

    // pre-issue G for step 0
    {
        const int t0 = (d == 0) ? 0 : (Tsz - 1);
        cp16(gdst, g_G[d] + (size_t)(t0 * 32 + gb) * G4 + goff0);
        CP_COMMIT();
    }

    const int barid = 1 + wk;

    for (int s = 0; s < Tsz; s++) {
        const int p = s & 1;
        const int t = (d == 0) ? s : (Tsz - 1 - s);
        const __half* __restrict__ Ah = g_h16[p][d];

        // issue this half's 4 A tiles as separate commit groups
#pragma unroll
        for (int tl = 0; tl < 4; tl++) {
            const int kt = wk * 4 + tl;
            uint32_t dst = smb + OFF_A + kt * R_SA + aOffT;
            const __half* src = Ah + (size_t)arow * Hsz + kt * 128 + ac2 * 8;
            cp16(dst, src);
            cp16(dst + 16, src + 8);
            CP_COMMIT();
        }

        float accA[2][4] = {};

#pragma unroll
        for (int tl = 0; tl < 4; tl++) {
            switch (tl) {
                case 0: CP_WAIT(3); break;
                case 1: CP_WAIT(2); break;
                case 2: CP_WAIT(1); break;
                default: CP_WAIT(0); break;
            }
            BAR_SYNC(barid, 256);
            const int kt = wk * 4 + tl;
            const uint32_t stgA = smb + OFF_A + kt * R_SA;
            const uint32_t bres = smb + kt * R_TILEB;
#pragma unroll
            for (int kc = 0; kc < 8; kc++) {
                uint32_t ah[4], bh[4];
                ldm4(ah, stgA + aRowOff + (uint32_t)((kc * 2 + acg) * 16));
                ldm4(bh, bres + bRowOff + (uint32_t)((kc * 2 + bk8) * 16));
                mma16816(accA[0], ah, &bh[0]);
                mma16816(accA[1], ah, &bh[2]);
            }
        }
        __syncthreads();   // both halves done; all G cp.async visible

        // epilogue: half 0 adds into gates_s (holds G); half 1 stores gates2_s
        {
            const int er = lid >> 2, ec = (lid & 3) * 2;
            const int b0 = wm * 16 + er, b1 = b0 + 8;
            if (wk == 0) {
#pragma unroll
                for (int ni = 0; ni < 2; ni++) {
                    int col = wn * 16 + ni * 8 + ec;
                    gates_s[b0 * GATE_P + col]     += accA[ni][0];
                    gates_s[b0 * GATE_P + col + 1] += accA[ni][1];
                    gates_s[b1 * GATE_P + col]     += accA[ni][2];
                    gates_s[b1 * GATE_P + col + 1] += accA[ni][3];
                }
            } else {
#pragma unroll
                for (int ni = 0; ni < 2; ni++) {
                    int col = wn * 16 + ni * 8 + ec;
                    gates2_s[b0 * GATE_P + col]     = accA[ni][0];
                    gates2_s[b0 * GATE_P + col + 1] = accA[ni][1];
                    gates2_s[b1 * GATE_P + col]     = accA[ni][2];
                    gates2_s[b1 * GATE_P + col + 1] = accA[ni][3];
                }
            }
        }
        __syncthreads();

        // cell update: 1 (b, hl) per thread
        const int np = p ^ 1;
        {
            int b = tid >> 4, hl = tid & 15;
            float gi = gates_s[b * GATE_P + 0 * 16 + hl] + gates2_s[b * GATE_P + 0 * 16 + hl];
            float gf = gates_s[b * GATE_P + 1 * 16 + hl] + gates2_s[b * GATE_P + 1 * 16 + hl];
            float gg = gates_s[b * GATE_P + 2 * 16 + hl] + gates2_s[b * GATE_P + 2 * 16 + hl];
            float go = gates_s[b * GATE_P + 3 * 16 + hl] + gates2_s[b * GATE_P + 3 * 16 + hl];
            float iv = sigf(gi), fv = sigf(gf), gv = tanhf(gg), ov = sigf(go);
            float cc = c_s[tid];
            float cn = fv * cc + iv * gv;
            float hn = ov * tanhf(cn);
            c_s[tid] = cn;

            int col = x * 16 + hl;
            g_h16[np][d][b * Hsz + col] = __float2half(hn);

            if (layer == 0) {
                g_A16[d][(size_t)(t * 32 + b) * Hsz + col] = __float2half(hn);
            } else {
                outp[((size_t)b * Tsz + t) * (2 * Hsz) + (size_t)d * Hsz + col] = hn;
                if (extra) {
                    outp[(size_t)Bsz * Tsz * 2 * Hsz + (size_t)d * Bsz * Tsz * Hsz
                         + ((size_t)b * Tsz + t) * Hsz + col] = hn;
                }
            }
        }
        __syncthreads();   // gates_s reads done before next step's G overwrite

        // pre-issue G for step s+1 (independent of h)
        if (s + 1 < Tsz) {
            const int tn = (d == 0) ? (s + 1) : (Tsz - 2 - s);
            cp16(gdst, g_G[d] + (size_t)(tn * 32 + gb) * G4 + goff0);
            CP_COMMIT();
        }

        grid_barrier_dir(d, x);
    }
}

extern "C" void kernel_launch(void* const* d_in, const int* in_sizes, int n_in,
                              void* d_out, int out_size) {
    const float* x     = (const float*)d_in[0];
    const float* Wih_f = (const float*)d_in[1];
    const float* Whh_f = (const float*)d_in[2];
    const float* b_f   = (const float*)d_in[3];
    const float* Wih_b = (const float*)d_in[4];
    const float* Whh_b = (const float*)d_in[5];
    const float* b_b   = (const float*)d_in[6];
    float* out = (float*)d_out;

    const long long full = (long long)Bsz * Tsz * 4 * Hsz;
    int extra = ((long long)out_size >= full) ? 1 : 0;

    static int attr_done = 0;
    if (!attr_done) {
        cudaFuncSetAttribute(tc_gemm_kernel,
                             cudaFuncAttributeMaxDynamicSharedMemorySize, SMEM_GEMM);
        cudaFuncSetAttribute(lstm_hmma_kernel,
                             cudaFuncAttributeMaxDynamicSharedMemorySize, SMEM_R);
        attr_done = 1;
    }

    dim3 gemmGrid(G4 / NT, MROWS / MT, 2);   // (32, 128, 2)
    dim3 stepGrid(64, 2);                    // 128 co-resident blocks

    conv_x_kernel<<<2048, 256>>>(x);
    for (int layer = 0; layer < 2; layer++) {
        conv_w_kernel<<<2048, 256>>>(Wih_f, Wih_b, layer);
        conv_rw_kernel<<<2048, 256>>>(Whh_f, Whh_b, layer);
        tc_gemm_kernel<<<gemmGrid, 256, SMEM_GEMM>>>(b_f, b_b, layer);
        lstm_hmma_kernel<<<stepGrid, 512, SMEM_R>>>(layer, out, extra);
    }
}

// round 17
// speedup vs baseline: 1.1522x; 1.0013x over previous
#include <cuda_runtime.h>
#include <cuda_fp16.h>
#include <math.h>
#include <stdint.h>

// BiRNN (2-layer bidirectional LSTM), B=32, T=512, H=1024.
// Round 17: recurrent kernel holds Whh fragments in REGISTERS (loaded once)
// — per-step smem traffic is A only. 16 warps = 4 K-quarters x 4 n-warps,
// warp tile m32 x n16 x K256. Four per-quarter gate buffers summed at the
// cell update. GEMM unchanged from round 14/16.

#define Bsz 32
#define Tsz 512
#define Hsz 1024
#define G4  4096
#define MROWS (Tsz * Bsz) // 16384

// big input GEMM tiling (two-stage, single W pass) — proven
#define MT 128
#define NT 128
#define KT 32
#define KP 40
#define BUFB (MT * KP * 2)        // 10240
#define STAGEB (2 * BUFB)         // A, W = 20480
#define SMEM_GEMM (2 * STAGEB)    // 40960

// recurrent tiling
#define RPB 272                          // row pitch bytes (128 fp16 + pad)
#define R_SA (32 * RPB)                  // one A tile: 8704
#define R_TILEB (64 * RPB)               // one B tile: 17408
#define R_BAREA (8 * R_TILEB)            // B prologue area: 139264
// post-prologue reuse of the same smem:
#define OFF_A 0                          // A tiles: 8 x 8704 = 69632
#define OFF_GATES (8 * R_SA)             // 4 gate buffers x 8704 = 34816
#define GATE_P 68
#define GBUF 8704
#define OFF_C (OFF_GATES + 4 * GBUF)     // 104448
#define SMEM_R R_BAREA                   // 139264

// ---------------- device globals -------------------------------------------
__device__ float g_G[2][(size_t)MROWS * G4];
__device__ __align__(256) __half g_A16[2][(size_t)MROWS * Hsz];
__device__ __align__(256) __half g_Wh16[2][(size_t)G4 * Hsz];
__device__ __align__(256) __half g_Rh16[2][(size_t)G4 * Hsz];
__device__ __align__(256) __half g_h16[2][2][Bsz * Hsz];
__device__ unsigned g_dcnt[2][4][64];
__device__ unsigned g_dcnt2[2][64];
__device__ volatile unsigned g_dgen[2][64];

// ---------------- helpers ---------------------------------------------------
__device__ __forceinline__ uint32_t smem_u32(const void* p) {
    uint32_t a;
    asm("{ .reg .u64 t; cvta.to.shared.u64 t, %1; cvt.u32.u64 %0, t; }" : "=r"(a) : "l"(p));
    return a;
}
__device__ __forceinline__ void cp16(uint32_t dst, const void* src) {
    asm volatile("cp.async.cg.shared.global [%0], [%1], 16;" :: "r"(dst), "l"(src));
}
#define CP_COMMIT() asm volatile("cp.async.commit_group;" ::: "memory")
#define CP_WAIT(n)  asm volatile("cp.async.wait_group %0;" :: "n"(n) : "memory")
#define BAR_SYNC(id, cnt) asm volatile("bar.sync %0, %1;" :: "r"(id), "r"(cnt) : "memory")

__device__ __forceinline__ void ldm4(uint32_t* r, uint32_t a) {
    asm volatile("ldmatrix.sync.aligned.m8n8.x4.shared.b16 {%0,%1,%2,%3}, [%4];"
        : "=r"(r[0]), "=r"(r[1]), "=r"(r[2]), "=r"(r[3]) : "r"(a));
}
__device__ __forceinline__ void mma16816(float* d, const uint32_t* a, const uint32_t* b) {
    asm volatile(
        "mma.sync.aligned.m16n8k16.row.col.f32.f16.f16.f32 "
        "{%0,%1,%2,%3}, {%4,%5,%6,%7}, {%8,%9}, {%0,%1,%2,%3};"
        : "+f"(d[0]), "+f"(d[1]), "+f"(d[2]), "+f"(d[3])
        : "r"(a[0]), "r"(a[1]), "r"(a[2]), "r"(a[3]), "r"(b[0]), "r"(b[1]));
}

__device__ __forceinline__ void grid_barrier_dir(int d, int xb) {
    __syncthreads();
    if (threadIdx.x == 0) {
        __threadfence();
        unsigned gen = g_dgen[d][0];
        unsigned r = atomicAdd(&g_dcnt[d][xb & 3][0], 1u);
        bool released = false;
        if (r == 15) {
            unsigned r2 = atomicAdd(&g_dcnt2[d][0], 1u);
            if (r2 == 3) {
                g_dcnt[d][0][0] = 0; g_dcnt[d][1][0] = 0;
                g_dcnt[d][2][0] = 0; g_dcnt[d][3][0] = 0;
                g_dcnt2[d][0] = 0;
                __threadfence();
                g_dgen[d][0] = gen + 1;
                released = true;
            }
        }
        if (!released) { while (g_dgen[d][0] == gen) { } }
        __threadfence();
    }
    __syncthreads();
}

__device__ __forceinline__ float sigf(float v) { return 1.0f / (1.0f + __expf(-v)); }

// ---------------- conversion kernels ---------------------------------------
__global__ void conv_x_kernel(const float* __restrict__ x) {
    const size_t N = (size_t)MROWS * Hsz;
    for (size_t i = blockIdx.x * blockDim.x + threadIdx.x; i < N; i += (size_t)gridDim.x * blockDim.x) {
        int r = (int)(i >> 10), h = (int)(i & 1023);
        int b = r & 31, t = r >> 5;
        g_A16[0][i] = __float2half(x[((size_t)b * Tsz + t) * Hsz + h]);
    }
}

__global__ void conv_w_kernel(const float* __restrict__ Wf, const float* __restrict__ Wb, int layer) {
    const size_t N = (size_t)G4 * Hsz;
    for (size_t i = blockIdx.x * blockDim.x + threadIdx.x; i < 2 * N; i += (size_t)gridDim.x * blockDim.x) {
        int d = i >= N;
        size_t j = d ? i - N : i;
        g_Wh16[d][j] = __float2half((d ? Wb : Wf)[(size_t)layer * N + j]);
    }
}

__global__ void conv_rw_kernel(const float* __restrict__ Wf, const float* __restrict__ Wb, int layer) {
    const size_t N = (size_t)G4 * Hsz;
    for (size_t i = blockIdx.x * blockDim.x + threadIdx.x; i < 2 * N; i += (size_t)gridDim.x * blockDim.x) {
        int d = i >= N;
        size_t j = d ? i - N : i;
        int r = (int)(j >> 10), k = (int)(j & 1023);
        int g = r >> 10, h = r & 1023;
        int nr = (h >> 4) * 64 + g * 16 + (h & 15);
        g_Rh16[d][(size_t)nr * Hsz + k] = __float2half((d ? Wb : Wf)[(size_t)layer * N + j]);
    }
}

// ---------------- HMMA big input GEMM (fp16, 1 pass, KT=32, 2-stage) -------
__global__ void __launch_bounds__(256, 2) tc_gemm_kernel(
    const float* __restrict__ b_f, const float* __restrict__ b_b, int layer)
{
    extern __shared__ __align__(16) char sm[];
    const int d = blockIdx.z;
    const int mBlk = blockIdx.y * MT;
    const int nBlk = blockIdx.x * NT;
    const int tid = threadIdx.x, wid = tid >> 5, lid = tid & 31;

    const int aSel = (layer == 0) ? 0 : d;
    const __half* __restrict__ Aa = g_A16[aSel] + (size_t)mBlk * Hsz;
    const __half* __restrict__ Bw = g_Wh16[d] + (size_t)nBlk * Hsz;
    const float* __restrict__ bias = (d == 0 ? b_f : b_b) + (size_t)layer * G4;

    const uint32_t smb = smem_u32(sm);

    const int lr0 = tid >> 2, lc0 = (tid & 3) * 8;
    const int lr1 = (tid + 256) >> 2;

    const int wm = wid & 1, wn = wid >> 1;
    const int ar = lid & 15, acg = lid >> 4;
    const int bnr = ((lid & 16) >> 1) | (lid & 7);
    const int bko = lid & 8;

    float acc[4][4][4] = {};

    {
        const uint32_t base = smb;
        uint32_t d0 = base + (uint32_t)(lr0 * KP + lc0) * 2;
        uint32_t d1 = base + (uint32_t)(lr1 * KP + lc0) * 2;
        size_t s0 = (size_t)lr0 * Hsz + lc0;
        size_t s1 = (size_t)lr1 * Hsz + lc0;
        cp16(d0 + 0 * BUFB, Aa + s0); cp16(d1 + 0 * BUFB, Aa + s1);
        cp16(d0 + 1 * BUFB, Bw + s0); cp16(d1 + 1 * BUFB, Bw + s1);
        CP_COMMIT();
    }

    const int NSTG = Hsz / KT; // 32
    for (int s = 0; s < NSTG; s++) {
        if (s + 1 < NSTG) {
            const int k0 = (s + 1) * KT;
            const uint32_t base = smb + ((s + 1) & 1) * STAGEB;
            uint32_t d0 = base + (uint32_t)(lr0 * KP + lc0) * 2;
            uint32_t d1 = base + (uint32_t)(lr1 * KP + lc0) * 2;
            size_t s0 = (size_t)lr0 * Hsz + k0 + lc0;
            size_t s1 = (size_t)lr1 * Hsz + k0 + lc0;
            cp16(d0 + 0 * BUFB, Aa + s0); cp16(d1 + 0 * BUFB, Aa + s1);
            cp16(d0 + 1 * BUFB, Bw + s0); cp16(d1 + 1 * BUFB, Bw + s1);
            CP_COMMIT();
            CP_WAIT(1);
        } else {
            CP_WAIT(0);
        }
        __syncthreads();

        const uint32_t base = smb + (s & 1) * STAGEB;
#pragma unroll
        for (int kc = 0; kc < 2; kc++) {
            uint32_t ah[4][4], bh[2][4];
#pragma unroll
            for (int mi = 0; mi < 4; mi++) {
                uint32_t ao = base + (uint32_t)((wm * 64 + mi * 16 + ar) * KP + kc * 16 + acg * 8) * 2;
                ldm4(ah[mi], ao);
            }
#pragma unroll
            for (int g = 0; g < 2; g++) {
                uint32_t bo = (uint32_t)((wn * 32 + g * 16 + bnr) * KP + kc * 16 + bko) * 2;
                ldm4(bh[g], base + BUFB + bo);
            }
#pragma unroll
            for (int mi = 0; mi < 4; mi++)
#pragma unroll
                for (int ni = 0; ni < 4; ni++)
                    mma16816(acc[mi][ni], ah[mi], &bh[ni >> 1][(ni & 1) * 2]);
        }
        __syncthreads();
    }

    const int er = lid >> 2, ec = (lid & 3) * 2;
#pragma unroll
    for (int mi = 0; mi < 4; mi++) {
#pragma unroll
        for (int ni = 0; ni < 4; ni++) {
            int gm = mBlk + wm * 64 + mi * 16 + er;
            int gn = nBlk + wn * 32 + ni * 8 + ec;
            float bv0 = bias[gn], bv1 = bias[gn + 1];
            float* p0 = g_G[d] + (size_t)gm * G4 + gn;
            p0[0] = acc[mi][ni][0] + bv0;
            p0[1] = acc[mi][ni][1] + bv1;
            float* p1 = p0 + (size_t)8 * G4;
            p1[0] = acc[mi][ni][2] + bv0;
            p1[1] = acc[mi][ni][3] + bv1;
        }
    }
}

// ---------------- persistent HMMA recurrent LSTM ---------------------------
// Grid (64, 2), 512 threads / 16 warps = 4 K-quarters (wq) x 4 n-warps (wn).
// Warp tile m32 x n16 x K256. B (Whh) fragments live in registers, loaded
// once in the prologue. Per-step smem traffic: A only + gate buffers.
__global__ void __launch_bounds__(512, 1) lstm_hmma_kernel(
    int layer, float* __restrict__ outp, int extra)
{
    extern __shared__ __align__(16) char rsm[];
    const int x = blockIdx.x, d = blockIdx.y;
    const int tid = threadIdx.x, wid = tid >> 5, lid = tid & 31;
    const int wq = wid >> 2;       // K quarter 0..3
    const int wn = wid & 3;        // n warp 0..3

    const uint32_t smb = smem_u32(rsm);
    float* c_s = (float*)(rsm + OFF_C);

    const __half* __restrict__ Bsrc = g_Rh16[d] + (size_t)(x * 64) * Hsz;

    // ---- prologue: load full B (8 tiles) into smem, frag into registers ----
    {
        const int brow = tid >> 3, bc2 = (tid & 7) * 2;
#pragma unroll
        for (int kt = 0; kt < 8; kt++) {
            uint32_t dst = smb + kt * R_TILEB + (uint32_t)(brow * RPB + bc2 * 16);
            const __half* src = Bsrc + (size_t)brow * Hsz + kt * 128 + bc2 * 8;
            cp16(dst, src);
            cp16(dst + 16, src + 8);
        }
        CP_COMMIT();
        CP_WAIT(0);
        __syncthreads();
    }

    const int bnr = ((lid & 16) >> 1) | (lid & 7);
    const int bk8 = (lid & 8) >> 3;
    const uint32_t bRowOff = (uint32_t)((wn * 16 + bnr) * RPB);

    uint32_t bfrag[16][4];
#pragma unroll
    for (int c = 0; c < 16; c++) {
        const int tile = 2 * wq + (c >> 3), cc = c & 7;
        ldm4(bfrag[c], smb + tile * R_TILEB + bRowOff + (uint32_t)((cc * 2 + bk8) * 16));
    }
    __syncthreads();   // all fragging done before smem is reused for A/gates

    // zero h (both parities) slice + c
    {
        int b = tid >> 4, col = x * 16 + (tid & 15);
        g_h16[0][d][b * Hsz + col] = __float2half(0.f);
        g_h16[1][d][b * Hsz + col] = __float2half(0.f);
        c_s[tid] = 0.f;
    }

    // A fragment maps (warp covers all 32 rows: two m16 tiles)
    const int ar = lid & 15, acg = lid >> 4;
    const uint32_t aRowOff0 = (uint32_t)(ar * RPB);
    const uint32_t aRowOff1 = (uint32_t)((16 + ar) * RPB);

    // A issue map: per-quarter 128 threads load the quarter's 2 tiles
    const int h127 = tid & 127;
    const int arow = h127 >> 2, ac4 = (h127 & 3) * 4;
    const uint32_t aOffT = (uint32_t)(arow * RPB + ac4 * 16);

    // G prefetch map -> gate buffer 0
    const int gb = tid >> 4, gch = tid & 15;
    const uint32_t gdst = smb + OFF_GATES + (uint32_t)(gb * GATE_P + gch * 4) * 4;
    const size_t goff0 = (size_t)(gch >> 2) * 1024 + x * 16 + (gch & 3) * 4;

    // pre-issue G for step 0
    {
        const int t0 = (d == 0) ? 0 : (Tsz - 1);
        cp16(gdst, g_G[d] + (size_t)(t0 * 32 + gb) * G4 + goff0);
        CP_COMMIT();
    }
    grid_barrier_dir(d, x);

    const int barid = 1 + wq;
    float* gq = (float*)(rsm + OFF_GATES + wq * GBUF);

    for (int s = 0; s < Tsz; s++) {
        const int p = s & 1;
        const int t = (d == 0) ? s : (Tsz - 1 - s);
        const __half* __restrict__ Ah = g_h16[p][d];

        // issue this quarter's 2 A tiles (2 commit groups)
#pragma unroll
        for (int tl = 0; tl < 2; tl++) {
            const int kt = 2 * wq + tl;
            uint32_t dst = smb + OFF_A + kt * R_SA + aOffT;
            const __half* src = Ah + (size_t)arow * Hsz + kt * 128 + ac4 * 8;
            cp16(dst, src);       cp16(dst + 16, src + 8);
            cp16(dst + 32, src + 16); cp16(dst + 48, src + 24);
            CP_COMMIT();
        }

        float acc[2][2][4] = {};   // [m-tile][n8][4]

        // first half: tile 2wq (chunks 0..7)
        CP_WAIT(1);
        BAR_SYNC(barid, 128);
        {
            const uint32_t stg = smb + OFF_A + (2 * wq) * R_SA;
#pragma unroll
            for (int cc = 0; cc < 8; cc++) {
                uint32_t a0[4], a1[4];
                uint32_t co = (uint32_t)((cc * 2 + acg) * 16);
                ldm4(a0, stg + aRowOff0 + co);
                ldm4(a1, stg + aRowOff1 + co);
                mma16816(acc[0][0], a0, &bfrag[cc][0]);
                mma16816(acc[0][1], a0, &bfrag[cc][2]);
                mma16816(acc[1][0], a1, &bfrag[cc][0]);
                mma16816(acc[1][1], a1, &bfrag[cc][2]);
            }
        }
        // second half: tile 2wq+1 (chunks 8..15)
        CP_WAIT(0);
        BAR_SYNC(barid, 128);
        {
            const uint32_t stg = smb + OFF_A + (2 * wq + 1) * R_SA;
#pragma unroll
            for (int cc = 0; cc < 8; cc++) {
                uint32_t a0[4], a1[4];
                uint32_t co = (uint32_t)((cc * 2 + acg) * 16);
                ldm4(a0, stg + aRowOff0 + co);
                ldm4(a1, stg + aRowOff1 + co);
                mma16816(acc[0][0], a0, &bfrag[8 + cc][0]);
                mma16816(acc[0][1], a0, &bfrag[8 + cc][2]);
                mma16816(acc[1][0], a1, &bfrag[8 + cc][0]);
                mma16816(acc[1][1], a1, &bfrag[8 + cc][2]);
            }
        }
        __syncthreads();   // all quarters done; G cp.async landed (waited above)

        // epilogue: quarter 0 adds into buffer 0 (holds G); others store
        {
            const int er = lid >> 2, ec = (lid & 3) * 2;
#pragma unroll
            for (int mi = 0; mi < 2; mi++) {
                const int b0 = mi * 16 + er, b1 = b0 + 8;
#pragma unroll
                for (int j = 0; j < 2; j++) {
                    int col = wn * 16 + j * 8 + ec;
                    if (wq == 0) {
                        gq[b0 * GATE_P + col]     += acc[mi][j][0];
                        gq[b0 * GATE_P + col + 1] += acc[mi][j][1];
                        gq[b1 * GATE_P + col]     += acc[mi][j][2];
                        gq[b1 * GATE_P + col + 1] += acc[mi][j][3];
                    } else {
                        gq[b0 * GATE_P + col]     = acc[mi][j][0];
                        gq[b0 * GATE_P + col + 1] = acc[mi][j][1];
                        gq[b1 * GATE_P + col]     = acc[mi][j][2];
                        gq[b1 * GATE_P + col + 1] = acc[mi][j][3];
                    }
                }
            }
        }
        __syncthreads();

        // cell update: 1 (b, hl) per thread; sum the 4 quarter buffers
        const int np = p ^ 1;
        {
            int b = tid >> 4, hl = tid & 15;
            float* g0 = (float*)(rsm + OFF_GATES);
            float* g1 = (float*)(rsm + OFF_GATES + GBUF);
            float* g2 = (float*)(rsm + OFF_GATES + 2 * GBUF);
            float* g3 = (float*)(rsm + OFF_GATES + 3 * GBUF);
            int i0 = b * GATE_P + 0 * 16 + hl;
            int i1 = b * GATE_P + 1 * 16 + hl;
            int i2 = b * GATE_P + 2 * 16 + hl;
            int i3 = b * GATE_P + 3 * 16 + hl;
            float gi = g0[i0] + g1[i0] + g2[i0] + g3[i0];
            float gf = g0[i1] + g1[i1] + g2[i1] + g3[i1];
            float gg = g0[i2] + g1[i2] + g2[i2] + g3[i2];
            float go = g0[i3] + g1[i3] + g2[i3] + g3[i3];
            float iv = sigf(gi), fv = sigf(gf), gv = tanhf(gg), ov = sigf(go);
            float cc = c_s[tid];
            float cn = fv * cc + iv * gv;
            float hn = ov * tanhf(cn);
            c_s[tid] = cn;

            int col = x * 16 + hl;
            g_h16[np][d][b * Hsz + col] = __float2half(hn);

            if (layer == 0) {
                g_A16[d][(size_t)(t * 32 + b) * Hsz + col] = __float2half(hn);
            } else {
                outp[((size_t)b * Tsz + t) * (2 * Hsz) + (size_t)d * Hsz + col] = hn;
                if (extra) {
                    outp[(size_t)Bsz * Tsz * 2 * Hsz + (size_t)d * Bsz * Tsz * Hsz
                         + ((size_t)b * Tsz + t) * Hsz + col] = hn;
                }
            }
        }
        __syncthreads();   // buffer reads done before next step's G overwrite

        // pre-issue G for step s+1 (independent of h)
        if (s + 1 < Tsz) {
            const int tn = (d == 0) ? (s + 1) : (Tsz - 2 - s);
            cp16(gdst, g_G[d] + (size_t)(tn * 32 + gb) * G4 + goff0);
            CP_COMMIT();
        }

        grid_barrier_dir(d, x);
    }
}

extern "C" void kernel_launch(void* const* d_in, const int* in_sizes, int n_in,
                              void* d_out, int out_size) {
    const float* x     = (const float*)d_in[0];
    const float* Wih_f = (const float*)d_in[1];
    const float* Whh_f = (const float*)d_in[2];
    const float* b_f   = (const float*)d_in[3];
    const float* Wih_b = (const float*)d_in[4];
    const float* Whh_b = (const float*)d_in[5];
    const float* b_b   = (const float*)d_in[6];
    float* out = (float*)d_out;

    const long long full = (long long)Bsz * Tsz * 4 * Hsz;
    int extra = ((long long)out_size >= full) ? 1 : 0;

    static int attr_done = 0;
    if (!attr_done) {
        cudaFuncSetAttribute(tc_gemm_kernel,
                             cudaFuncAttributeMaxDynamicSharedMemorySize, SMEM_GEMM);
        cudaFuncSetAttribute(lstm_hmma_kernel,
                             cudaFuncAttributeMaxDynamicSharedMemorySize, SMEM_R);
        attr_done = 1;
    }

    dim3 gemmGrid(G4 / NT, MROWS / MT, 2);   // (32, 128, 2)
    dim3 stepGrid(64, 2);                    // 128 co-resident blocks

    conv_x_kernel<<<2048, 256>>>(x);
    for (int layer = 0; layer < 2; layer++) {
        conv_w_kernel<<<2048, 256>>>(Wih_f, Wih_b, layer);
        conv_rw_kernel<<<2048, 256>>>(Whh_f, Whh_b, layer);
        tc_gemm_kernel<<<gemmGrid, 256, SMEM_GEMM>>>(b_f, b_b, layer);
        lstm_hmma_kernel<<<stepGrid, 512, SMEM_R>>>(layer, out, extra);
    }
}